// round 2
// baseline (speedup 1.0000x reference)
#include <cuda_runtime.h>
#include <cuda_bf16.h>

// MHC fused, persistent version.
// Grid = #SMs, 1 CTA/SM (512 thr, <=128 regs). Each CTA loops rows strided by
// gridDim with register ping-pong prefetch: loads for row r+grid are issued
// before processing row r, keeping DRAM busy across the reduce barrier.

#define N_STREAMS 4
#define C_DIM     4096
#define C4        (C_DIM / 4)
#define THREADS   512
#define EPS       1e-6f
#define SINKHORN_ITERS 3

__device__ __forceinline__ void load_row(const float4* __restrict__ x4,
                                         int row, int tid,
                                         float4 (&v)[N_STREAMS][2])
{
    const float4* __restrict__ p = x4 + (size_t)row * (N_STREAMS * C4);
    #pragma unroll
    for (int n = 0; n < N_STREAMS; n++) {
        v[n][0] = p[n * C4 + tid];
        v[n][1] = p[n * C4 + tid + THREADS];
    }
}

__device__ __forceinline__ void process_row(
    const float4 (&v)[N_STREAMS][2],
    const float (&hpre)[N_STREAMS], const float (&hpost)[N_STREAMS],
    const float (&P)[N_STREAMS][N_STREAMS],
    const float* __restrict__ wsh,          // rmsnorm weight in smem
    volatile float* __restrict__ wsum,      // 16-slot parity slice
    float4* __restrict__ out4, int row,
    int tid, int lane, int wid)
{
    // Unpack register float4s
    float va[N_STREAMS][8];
    #pragma unroll
    for (int n = 0; n < N_STREAMS; n++) {
        va[n][0] = v[n][0].x; va[n][1] = v[n][0].y;
        va[n][2] = v[n][0].z; va[n][3] = v[n][0].w;
        va[n][4] = v[n][1].x; va[n][5] = v[n][1].y;
        va[n][6] = v[n][1].z; va[n][7] = v[n][1].w;
    }

    // x_agg (sigmoid-gated sum over streams), bf16 round-trip, sum of squares
    float agg[8];
    float ss = 0.0f;
    #pragma unroll
    for (int e = 0; e < 8; e++) {
        float a = hpre[0] * va[0][e] + hpre[1] * va[1][e]
                + hpre[2] * va[2][e] + hpre[3] * va[3][e];
        a = __bfloat162float(__float2bfloat16_rn(a));
        agg[e] = a;
        ss += a * a;
    }

    // Warp reduce + single-barrier block reduce (parity slot)
    #pragma unroll
    for (int o = 16; o > 0; o >>= 1)
        ss += __shfl_xor_sync(0xffffffffu, ss, o);
    if (lane == 0) wsum[wid] = ss;
    __syncthreads();
    float tot = 0.0f;
    #pragma unroll
    for (int i = 0; i < THREADS / 32; i++) tot += wsum[i];
    const float rinv = rsqrtf(tot * (1.0f / C_DIM) + EPS);

    // t[e] = agg_bf * w[c]   (w from smem)
    const float4 w0 = reinterpret_cast<const float4*>(wsh)[tid];
    const float4 w1 = reinterpret_cast<const float4*>(wsh)[tid + THREADS];
    float t[8];
    t[0] = agg[0] * w0.x; t[1] = agg[1] * w0.y;
    t[2] = agg[2] * w0.z; t[3] = agg[3] * w0.w;
    t[4] = agg[4] * w1.x; t[5] = agg[5] * w1.y;
    t[6] = agg[6] * w1.z; t[7] = agg[7] * w1.w;

    // out[i][e] = sum_j P[i][j]*x[j][e] + (hpost[i]*rinv) * t[e]
    float4* __restrict__ orow = out4 + (size_t)row * (N_STREAMS * C4);
    #pragma unroll
    for (int i = 0; i < N_STREAMS; i++) {
        const float h = hpost[i] * rinv;
        float o[8];
        #pragma unroll
        for (int e = 0; e < 8; e++) {
            o[e] = P[i][0] * va[0][e] + P[i][1] * va[1][e]
                 + P[i][2] * va[2][e] + P[i][3] * va[3][e]
                 + h * t[e];
        }
        orow[i * C4 + tid]           = make_float4(o[0], o[1], o[2], o[3]);
        orow[i * C4 + tid + THREADS] = make_float4(o[4], o[5], o[6], o[7]);
    }
}

__global__ __launch_bounds__(THREADS, 1)
void mhc_persistent_kernel(const float* __restrict__ x,
                           const float* __restrict__ w,
                           const float* __restrict__ H_pre,
                           const float* __restrict__ H_post,
                           const float* __restrict__ H_res,
                           float* __restrict__ out, int B)
{
    __shared__ float wsh[C_DIM];
    __shared__ float wsum[2][THREADS / 32];

    const int tid = threadIdx.x, lane = tid & 31, wid = tid >> 5;

    // Stage rmsnorm weight in smem (first barrier is inside process_row)
    reinterpret_cast<float4*>(wsh)[tid] =
        reinterpret_cast<const float4*>(w)[tid];
    reinterpret_cast<float4*>(wsh)[tid + THREADS] =
        reinterpret_cast<const float4*>(w)[tid + THREADS];

    // Tiny params: sigmoid gates + Sinkhorn (redundant per thread, registers)
    float hpre[N_STREAMS], hpost[N_STREAMS];
    #pragma unroll
    for (int i = 0; i < N_STREAMS; i++) {
        hpre[i]  = 1.0f / (1.0f + expf(-H_pre[i]));
        hpost[i] = 2.0f / (1.0f + expf(-H_post[i]));
    }
    float P[N_STREAMS][N_STREAMS];
    #pragma unroll
    for (int i = 0; i < N_STREAMS; i++)
        #pragma unroll
        for (int j = 0; j < N_STREAMS; j++)
            P[i][j] = expf(H_res[i * N_STREAMS + j]);
    #pragma unroll
    for (int it = 0; it < SINKHORN_ITERS; it++) {
        #pragma unroll
        for (int i = 0; i < N_STREAMS; i++) {
            float ri = 1.0f / (P[i][0] + P[i][1] + P[i][2] + P[i][3] + EPS);
            #pragma unroll
            for (int j = 0; j < N_STREAMS; j++) P[i][j] *= ri;
        }
        #pragma unroll
        for (int j = 0; j < N_STREAMS; j++) {
            float ci = 1.0f / (P[0][j] + P[1][j] + P[2][j] + P[3][j] + EPS);
            #pragma unroll
            for (int i = 0; i < N_STREAMS; i++) P[i][j] *= ci;
        }
    }

    const float4* __restrict__ x4 = reinterpret_cast<const float4*>(x);
    float4* __restrict__ out4     = reinterpret_cast<float4*>(out);

    // Persistent row loop, register ping-pong prefetch
    float4 bufA[N_STREAMS][2], bufB[N_STREAMS][2];
    const int stride = gridDim.x;
    int r = blockIdx.x;
    if (r < B) load_row(x4, r, tid, bufA);

    while (r < B) {
        int rn = r + stride;
        if (rn < B) load_row(x4, rn, tid, bufB);      // prefetch next
        process_row(bufA, hpre, hpost, P, wsh, wsum[0], out4, r,
                    tid, lane, wid);
        r = rn;
        if (r >= B) break;

        rn = r + stride;
        if (rn < B) load_row(x4, rn, tid, bufA);      // prefetch next
        process_row(bufB, hpre, hpost, P, wsh, wsum[1], out4, r,
                    tid, lane, wid);
        r = rn;
    }
}

extern "C" void kernel_launch(void* const* d_in, const int* in_sizes, int n_in,
                              void* d_out, int out_size)
{
    const float* x      = (const float*)d_in[0];
    const float* w      = (const float*)d_in[1];
    const float* H_pre  = (const float*)d_in[2];
    const float* H_post = (const float*)d_in[3];
    const float* H_res  = (const float*)d_in[4];
    float* out          = (float*)d_out;

    const int B = in_sizes[0] / (N_STREAMS * C_DIM);

    int dev = 0, nsm = 148;
    cudaGetDevice(&dev);
    cudaDeviceGetAttribute(&nsm, cudaDevAttrMultiProcessorCount, dev);

    mhc_persistent_kernel<<<nsm, THREADS>>>(x, w, H_pre, H_post, H_res, out, B);
}